// round 14
// baseline (speedup 1.0000x reference)
#include <cuda_runtime.h>
#include <cuda_fp16.h>
#include <cstdint>

// Problem constants
#define BB   2
#define TT   2048
#define CC   1024
#define HH   16
#define DD   64
#define MROWS (BB*TT)          // 4096
#define SCALE 0.125f           // 1/sqrt(64)

// Scratch (device globals). fp16 data stored as packed u32 (half2 pairs).
__device__ uint32_t g_xh [MROWS*CC/2];     // x fp16 [M][C]
__device__ uint32_t g_wqh[3*CC*CC/2];      // w_qkv^T fp16 [3C][C]  ([n][k])
__device__ uint32_t g_wph[CC*CC/2];        // w_proj^T fp16 [C][C]
__device__ uint32_t g_q  [BB*HH*TT*DD/2];  // [bh][t][d] fp16
__device__ uint32_t g_k  [BB*HH*TT*DD/2];  // [bh][t][d] fp16
__device__ uint32_t g_vt [BB*HH*DD*TT/2];  // V^T: [bh][d][t] fp16
__device__ uint32_t g_yh [MROWS*CC/2];     // attention out fp16 [M][C]

// ===========================================================================
// helpers
// ===========================================================================
__device__ __forceinline__ uint32_t pack_half2(float lo, float hi) {
    uint32_t u;
    asm("cvt.rn.f16x2.f32 %0, %1, %2;" : "=r"(u) : "f"(hi), "f"(lo));
    return u;
}

__device__ __forceinline__ void mma_f16_16x8x16(float* c, const uint32_t* a,
                                                const uint32_t* b) {
    asm volatile(
        "mma.sync.aligned.m16n8k16.row.col.f32.f16.f16.f32 "
        "{%0,%1,%2,%3}, {%4,%5,%6,%7}, {%8,%9}, {%0,%1,%2,%3};\n"
        : "+f"(c[0]), "+f"(c[1]), "+f"(c[2]), "+f"(c[3])
        : "r"(a[0]), "r"(a[1]), "r"(a[2]), "r"(a[3]),
          "r"(b[0]), "r"(b[1]));
}

__device__ __forceinline__ void ldsm_x4(uint32_t* r, uint32_t saddr) {
    asm volatile("ldmatrix.sync.aligned.m8n8.x4.shared.b16 {%0,%1,%2,%3}, [%4];"
        : "=r"(r[0]), "=r"(r[1]), "=r"(r[2]), "=r"(r[3]) : "r"(saddr));
}

__device__ __forceinline__ void cp_async16(uint32_t dst, const void* src) {
    asm volatile("cp.async.cg.shared.global [%0], [%1], 16;"
                 :: "r"(dst), "l"(src));
}
__device__ __forceinline__ void cp_commit() {
    asm volatile("cp.async.commit_group;" ::: "memory");
}
__device__ __forceinline__ void cp_wait2() {
    asm volatile("cp.async.wait_group 2;" ::: "memory");
}
__device__ __forceinline__ void cp_wait1() {
    asm volatile("cp.async.wait_group 1;" ::: "memory");
}

// ---------------------------------------------------------------------------
// Kernel 0a: fp32 -> fp16 bulk convert
// ---------------------------------------------------------------------------
__global__ __launch_bounds__(256) void conv_f16_kernel(
    const float4* __restrict__ in, uint2* __restrict__ out, int n4)
{
    int i = blockIdx.x * blockDim.x + threadIdx.x;
    int stride = gridDim.x * blockDim.x;
    for (; i < n4; i += stride) {
        float4 v = in[i];
        uint2 o;
        o.x = pack_half2(v.x, v.y);
        o.y = pack_half2(v.z, v.w);
        out[i] = o;
    }
}

// ---------------------------------------------------------------------------
// Kernel 0b: fp32 [K][N] -> fp16 [N][K] transpose (weights)
// ---------------------------------------------------------------------------
__global__ __launch_bounds__(256) void trans_f16_kernel(
    const float* __restrict__ in, uint32_t* __restrict__ out, int N, int K)
{
    __shared__ float ts[32][33];
    const int k0 = blockIdx.y * 32, n0 = blockIdx.x * 32;
    const int tx = threadIdx.x & 31, ty = threadIdx.x >> 5;
    #pragma unroll
    for (int j = 0; j < 4; j++)
        ts[ty + 8*j][tx] = in[(size_t)(k0 + ty + 8*j) * N + n0 + tx];
    __syncthreads();
    const int n = threadIdx.x >> 3, c = threadIdx.x & 7;
    out[(size_t)(n0 + n) * (K >> 1) + (k0 >> 1) + c] =
        pack_half2(ts[2*c][n], ts[2*c + 1][n]);
    out[(size_t)(n0 + n) * (K >> 1) + (k0 >> 1) + c + 8] =
        pack_half2(ts[2*c + 16][n], ts[2*c + 17][n]);
}

// ===========================================================================
// fp16 GEMM mainloop, cp.async 4-stage + ldmatrix (unchanged from R13).
// ===========================================================================
#define GP 20
#define GSTA (128*GP)
#define GST (2*GSTA)
#define NSTAGE 4
#define GEMM_SMEM_BYTES (NSTAGE * GST * 4)   // 81920 B

__device__ __forceinline__ void gemm_f16_mainloop(
    uint32_t* sm, const uint32_t* __restrict__ A,
    const uint32_t* __restrict__ B, float acc[2][8][4])
{
    const int tid = threadIdx.x;
    const int wid = tid >> 5, lane = tid & 31;
    const int warp_m = wid & 3;
    const int warp_n = wid >> 2;

    #pragma unroll
    for (int mi = 0; mi < 2; mi++)
        #pragma unroll
        for (int ni = 0; ni < 8; ni++)
            #pragma unroll
            for (int r = 0; r < 4; r++) acc[mi][ni][r] = 0.f;

    const int r0 = tid >> 2, s0 = tid & 3;
    const int r1 = (256 + tid) >> 2, s1 = tid & 3;
    const uint32_t smaddr = (uint32_t)__cvta_generic_to_shared(sm);

    #pragma unroll
    for (int s = 0; s < NSTAGE - 1; s++) {
        const uint32_t so = (uint32_t)(s * GST * 4);
        cp_async16(smaddr + so + (uint32_t)(r0 * GP + s0 * 4) * 4,
                   A + (size_t)r0 * (CC/2) + s * 16 + s0 * 4);
        cp_async16(smaddr + so + (uint32_t)(r1 * GP + s1 * 4) * 4,
                   A + (size_t)r1 * (CC/2) + s * 16 + s1 * 4);
        cp_async16(smaddr + so + (uint32_t)(GSTA + r0 * GP + s0 * 4) * 4,
                   B + (size_t)r0 * (CC/2) + s * 16 + s0 * 4);
        cp_async16(smaddr + so + (uint32_t)(GSTA + r1 * GP + s1 * 4) * 4,
                   B + (size_t)r1 * (CC/2) + s * 16 + s1 * 4);
        cp_commit();
    }

    const int lq = lane >> 3, lr = lane & 7;
    const int a_row  = warp_m * 32 + lr + 8 * (lq & 1);
    const int a_col  = 4 * (lq >> 1);
    const int b_row  = warp_n * 64 + lr + 8 * (lq >> 1);
    const int b_col  = 4 * (lq & 1);

    for (int c = 0; c < CC / 32; c++) {
        cp_wait2();
        __syncthreads();

        const uint32_t sa = smaddr + (uint32_t)((c & 3) * GST) * 4;
        const uint32_t sb = sa + (uint32_t)GSTA * 4;

        uint32_t af[2][2][4];
        #pragma unroll
        for (int mi = 0; mi < 2; mi++)
            #pragma unroll
            for (int ks = 0; ks < 2; ks++)
                ldsm_x4(af[mi][ks],
                        sa + (uint32_t)((a_row + mi * 16) * GP + ks * 8 + a_col) * 4);

        uint32_t bf[4][2][4];
        #pragma unroll
        for (int nfp = 0; nfp < 4; nfp++)
            #pragma unroll
            for (int ks = 0; ks < 2; ks++)
                ldsm_x4(bf[nfp][ks],
                        sb + (uint32_t)((b_row + nfp * 16) * GP + ks * 8 + b_col) * 4);

        #pragma unroll
        for (int mi = 0; mi < 2; mi++)
            #pragma unroll
            for (int nfp = 0; nfp < 4; nfp++)
                #pragma unroll
                for (int ks = 0; ks < 2; ks++) {
                    mma_f16_16x8x16(acc[mi][2 * nfp],     af[mi][ks], &bf[nfp][ks][0]);
                    mma_f16_16x8x16(acc[mi][2 * nfp + 1], af[mi][ks], &bf[nfp][ks][2]);
                }

        if (c + NSTAGE - 1 < CC / 32) {
            const int cn = c + NSTAGE - 1;
            const uint32_t so = (uint32_t)((cn & 3) * GST * 4);
            cp_async16(smaddr + so + (uint32_t)(r0 * GP + s0 * 4) * 4,
                       A + (size_t)r0 * (CC/2) + cn * 16 + s0 * 4);
            cp_async16(smaddr + so + (uint32_t)(r1 * GP + s1 * 4) * 4,
                       A + (size_t)r1 * (CC/2) + cn * 16 + s1 * 4);
            cp_async16(smaddr + so + (uint32_t)(GSTA + r0 * GP + s0 * 4) * 4,
                       B + (size_t)r0 * (CC/2) + cn * 16 + s0 * 4);
            cp_async16(smaddr + so + (uint32_t)(GSTA + r1 * GP + s1 * 4) * 4,
                       B + (size_t)r1 * (CC/2) + cn * 16 + s1 * 4);
        }
        cp_commit();
    }
}

// ---------------------------------------------------------------------------
// Kernel 1: QKV projection (unchanged from R13)
// ---------------------------------------------------------------------------
__global__ __launch_bounds__(256, 2) void qkv_mma_kernel()
{
    extern __shared__ uint32_t smu[];
    const int bx = blockIdx.x;
    const int by = blockIdx.y;
    const int tid = threadIdx.x;
    const int wid = tid >> 5, lane = tid & 31;
    const int warp_m = wid & 3, warp_n = wid >> 2;
    const int g = lane >> 2, t = lane & 3;

    float acc[2][8][4];
    gemm_f16_mainloop(smu, g_xh + (size_t)(by * 128) * (CC/2),
                      g_wqh + (size_t)(bx * 128) * (CC/2), acc);

    const int g3 = bx >> 3;
    if (g3 < 2) {
        uint32_t* dstbase = (g3 == 0) ? g_q : g_k;
        #pragma unroll
        for (int mi = 0; mi < 2; mi++) {
            #pragma unroll
            for (int rr = 0; rr < 2; rr++) {
                int m = by * 128 + warp_m * 32 + mi * 16 + g + rr * 8;
                int b = m >> 11, tloc = m & (TT - 1);
                #pragma unroll
                for (int ni = 0; ni < 8; ni++) {
                    int n = bx * 128 + warp_n * 64 + ni * 8 + 2 * t;
                    int rem = n & 1023;
                    int h = rem >> 6, d = rem & 63;
                    dstbase[(((size_t)(b * HH + h)) * TT + tloc) * (DD/2) + (d >> 1)] =
                        pack_half2(acc[mi][ni][rr * 2], acc[mi][ni][rr * 2 + 1]);
                }
            }
        }
    } else {
        unsigned short* vt = (unsigned short*)g_vt;
        #pragma unroll
        for (int mi = 0; mi < 2; mi++) {
            #pragma unroll
            for (int rr = 0; rr < 2; rr++) {
                int m = by * 128 + warp_m * 32 + mi * 16 + g + rr * 8;
                int b = m >> 11, tloc = m & (TT - 1);
                #pragma unroll
                for (int ni = 0; ni < 8; ni++) {
                    int n = bx * 128 + warp_n * 64 + ni * 8 + 2 * t;
                    int rem = n & 1023;
                    int h = rem >> 6, d = rem & 63;
                    size_t base = ((size_t)(b * HH + h) * DD + d) * TT + tloc;
                    vt[base]      = __half_as_ushort(__float2half_rn(acc[mi][ni][rr * 2]));
                    vt[base + TT] = __half_as_ushort(__float2half_rn(acc[mi][ni][rr * 2 + 1]));
                }
            }
        }
    }
}

// ---------------------------------------------------------------------------
// Kernel 3: out = y @ w_proj + b_proj (unchanged from R13)
// ---------------------------------------------------------------------------
__global__ __launch_bounds__(256, 2) void proj_mma_kernel(
    const float* __restrict__ bias, float* __restrict__ out)
{
    extern __shared__ uint32_t smu[];
    const int bx = blockIdx.x;
    const int by = blockIdx.y;
    const int tid = threadIdx.x;
    const int wid = tid >> 5, lane = tid & 31;
    const int warp_m = wid & 3, warp_n = wid >> 2;
    const int g = lane >> 2, t = lane & 3;

    float acc[2][8][4];
    gemm_f16_mainloop(smu, g_yh + (size_t)(by * 128) * (CC/2),
                      g_wph + (size_t)(bx * 128) * (CC/2), acc);

    #pragma unroll
    for (int mi = 0; mi < 2; mi++) {
        #pragma unroll
        for (int rr = 0; rr < 2; rr++) {
            int m = by * 128 + warp_m * 32 + mi * 16 + g + rr * 8;
            #pragma unroll
            for (int ni = 0; ni < 8; ni++) {
                int n = bx * 128 + warp_n * 64 + ni * 8 + 2 * t;
                float2 v2;
                v2.x = acc[mi][ni][rr * 2]     + bias[n];
                v2.y = acc[mi][ni][rr * 2 + 1] + bias[n + 1];
                *(float2*)&out[(size_t)m * CC + n] = v2;
            }
        }
    }
}

// ===========================================================================
// Flash attention, fp16 mma + cp.async 3-stage + ldmatrix.
// CTA: 128 q-rows of one (b,h), 256 threads, 8 warps x 16 rows. KTILE 64.
// Stage: K [64 key][32 d2] + V [64 d][32 t2], pitch ATP=36 u32.
// Tile = 512 x 16B chunks per operand; 2 chunks/thread/operand.
// ===========================================================================
#define ATP 36
#define AST (64*ATP*2)                    // stage u32 = 4608 (18432 B)
#define ANST 3
#define FA_SMEM_BYTES (ANST * AST * 4)    // 55296

__global__ __launch_bounds__(256, 2) void flash_attn_f16_kernel()
{
    extern __shared__ uint32_t smu[];
    const uint32_t smaddr = (uint32_t)__cvta_generic_to_shared(smu);

    const int qi = (int)gridDim.x - 1 - (int)blockIdx.x;   // heavy CTAs first
    const int bh = blockIdx.y;
    const int b = bh >> 4, h = bh & 15;
    const int tid = threadIdx.x;
    const int wid = tid >> 5, lane = tid & 31;
    const int g = lane >> 2, t = lane & 3;
    const int wbase = wid * 16;

    // ---- Q fragments straight from gmem ----
    const uint32_t* q0 = g_q + ((size_t)bh * TT + qi * 128 + wbase + g) * (DD/2);
    const uint32_t* q1 = q0 + 8 * (DD/2);
    uint32_t qf[4][4];
    #pragma unroll
    for (int ks = 0; ks < 4; ks++) {
        qf[ks][0] = q0[ks * 8 + t];
        qf[ks][1] = q1[ks * 8 + t];
        qf[ks][2] = q0[ks * 8 + t + 4];
        qf[ks][3] = q1[ks * 8 + t + 4];
    }

    const int nkt = 2 * qi + 2;

    // cp.async mapping: row0/row1 (+32), c = chunk-in-row
    const int arow0 = tid >> 3, ac = tid & 7;   // rows 0..31
    const int arow1 = arow0 + 32;
    const uint32_t kbase0 = (uint32_t)(arow0 * ATP + ac * 4) * 4;
    const uint32_t kbase1 = (uint32_t)(arow1 * ATP + ac * 4) * 4;
    const uint32_t voff   = (uint32_t)(64 * ATP) * 4;
    const uint32_t* kg0 = g_k  + ((size_t)bh * TT + arow0) * (DD/2) + ac * 4;
    const uint32_t* kg1 = g_k  + ((size_t)bh * TT + arow1) * (DD/2) + ac * 4;
    const uint32_t* vg0 = g_vt + ((size_t)bh * DD + arow0) * (TT/2) + ac * 4;
    const uint32_t* vg1 = g_vt + ((size_t)bh * DD + arow1) * (TT/2) + ac * 4;

    // prologue: tiles 0 and 1
    #pragma unroll
    for (int s = 0; s < 2; s++) {
        const uint32_t so = (uint32_t)(s * AST) * 4;
        cp_async16(smaddr + so + kbase0, kg0 + (size_t)s * 64 * (DD/2));
        cp_async16(smaddr + so + kbase1, kg1 + (size_t)s * 64 * (DD/2));
        cp_async16(smaddr + so + voff + kbase0, vg0 + s * 32);
        cp_async16(smaddr + so + voff + kbase1, vg1 + s * 32);
        cp_commit();
    }

    // ldmatrix lane addressing
    const int lq = lane >> 3, lr = lane & 7;
    const int f_row  = lr + 8 * (lq >> 1);   // + nfp*16
    const int f_col4 = 4 * (lq & 1);          // + ks*8

    float of[8][4];
    #pragma unroll
    for (int nf = 0; nf < 8; nf++)
        #pragma unroll
        for (int r = 0; r < 4; r++) of[nf][r] = 0.f;
    float m0 = -1e30f, m1 = -1e30f, l0 = 0.f, l1 = 0.f;

    const int qrow0 = qi * 128 + wbase + g;
    const int qrow1 = qrow0 + 8;

    for (int kt = 0; kt < nkt; kt++) {
        cp_wait1();
        __syncthreads();

        const uint32_t sk = smaddr + (uint32_t)((kt % ANST) * AST) * 4;
        const uint32_t sv = sk + voff;

        // ---- S = Q @ K^T ----
        float sf[8][4];
        #pragma unroll
        for (int nf = 0; nf < 8; nf++)
            #pragma unroll
            for (int r = 0; r < 4; r++) sf[nf][r] = 0.f;

        #pragma unroll
        for (int ks = 0; ks < 4; ks++) {
            #pragma unroll
            for (int nfp = 0; nfp < 4; nfp++) {
                uint32_t bfr[4];
                ldsm_x4(bfr, sk + (uint32_t)((nfp * 16 + f_row) * ATP + ks * 8 + f_col4) * 4);
                mma_f16_16x8x16(sf[2 * nfp],     qf[ks], &bfr[0]);
                mma_f16_16x8x16(sf[2 * nfp + 1], qf[ks], &bfr[2]);
            }
        }

        // ---- scale + causal mask ----
        const bool need_mask = (kt >= 2 * qi);
        #pragma unroll
        for (int nf = 0; nf < 8; nf++) {
            int kc0 = kt * 64 + nf * 8 + 2 * t;
            int kc1 = kc0 + 1;
            if (need_mask) {
                sf[nf][0] = (kc0 <= qrow0) ? sf[nf][0] * SCALE : -1e30f;
                sf[nf][1] = (kc1 <= qrow0) ? sf[nf][1] * SCALE : -1e30f;
                sf[nf][2] = (kc0 <= qrow1) ? sf[nf][2] * SCALE : -1e30f;
                sf[nf][3] = (kc1 <= qrow1) ? sf[nf][3] * SCALE : -1e30f;
            } else {
                sf[nf][0] *= SCALE; sf[nf][1] *= SCALE;
                sf[nf][2] *= SCALE; sf[nf][3] *= SCALE;
            }
        }

        // ---- online softmax ----
        float mx0 = -1e30f, mx1 = -1e30f;
        #pragma unroll
        for (int nf = 0; nf < 8; nf++) {
            mx0 = fmaxf(mx0, fmaxf(sf[nf][0], sf[nf][1]));
            mx1 = fmaxf(mx1, fmaxf(sf[nf][2], sf[nf][3]));
        }
        #pragma unroll
        for (int off = 1; off < 4; off <<= 1) {
            mx0 = fmaxf(mx0, __shfl_xor_sync(0xffffffffu, mx0, off));
            mx1 = fmaxf(mx1, __shfl_xor_sync(0xffffffffu, mx1, off));
        }
        float mn0 = fmaxf(m0, mx0), mn1 = fmaxf(m1, mx1);
        float a0 = __expf(m0 - mn0), a1 = __expf(m1 - mn1);
        m0 = mn0; m1 = mn1;

        float s0 = 0.f, s1 = 0.f;
        #pragma unroll
        for (int nf = 0; nf < 8; nf++) {
            sf[nf][0] = __expf(sf[nf][0] - mn0);
            sf[nf][1] = __expf(sf[nf][1] - mn0);
            sf[nf][2] = __expf(sf[nf][2] - mn1);
            sf[nf][3] = __expf(sf[nf][3] - mn1);
            s0 += sf[nf][0] + sf[nf][1];
            s1 += sf[nf][2] + sf[nf][3];
        }
        #pragma unroll
        for (int off = 1; off < 4; off <<= 1) {
            s0 += __shfl_xor_sync(0xffffffffu, s0, off);
            s1 += __shfl_xor_sync(0xffffffffu, s1, off);
        }
        l0 = l0 * a0 + s0;
        l1 = l1 * a1 + s1;

        // ---- P -> fp16 a-frags (registers only) ----
        uint32_t pf[4][4];
        #pragma unroll
        for (int ks = 0; ks < 4; ks++) {
            pf[ks][0] = pack_half2(sf[2*ks][0],     sf[2*ks][1]);
            pf[ks][1] = pack_half2(sf[2*ks][2],     sf[2*ks][3]);
            pf[ks][2] = pack_half2(sf[2*ks + 1][0], sf[2*ks + 1][1]);
            pf[ks][3] = pack_half2(sf[2*ks + 1][2], sf[2*ks + 1][3]);
        }

        // ---- rescale O, then O += P @ V ----
        #pragma unroll
        for (int nf = 0; nf < 8; nf++) {
            of[nf][0] *= a0; of[nf][1] *= a0;
            of[nf][2] *= a1; of[nf][3] *= a1;
        }
        #pragma unroll
        for (int ks = 0; ks < 4; ks++) {
            #pragma unroll
            for (int nfp = 0; nfp < 4; nfp++) {
                uint32_t bfr[4];
                ldsm_x4(bfr, sv + (uint32_t)((nfp * 16 + f_row) * ATP + ks * 8 + f_col4) * 4);
                mma_f16_16x8x16(of[2 * nfp],     pf[ks], &bfr[0]);
                mma_f16_16x8x16(of[2 * nfp + 1], pf[ks], &bfr[2]);
            }
        }

        // ---- issue tile kt+2 (stage read last at iteration kt-1, before
        //      this iteration's barrier -> safe) ----
        if (kt + 2 < nkt) {
            const int cn = kt + 2;
            const uint32_t so = (uint32_t)((cn % ANST) * AST) * 4;
            cp_async16(smaddr + so + kbase0, kg0 + (size_t)cn * 64 * (DD/2));
            cp_async16(smaddr + so + kbase1, kg1 + (size_t)cn * 64 * (DD/2));
            cp_async16(smaddr + so + voff + kbase0, vg0 + cn * 32);
            cp_async16(smaddr + so + voff + kbase1, vg1 + cn * 32);
        }
        cp_commit();   // unconditional: exact tail group counting
    }

    // ---- epilogue: normalize -> fp16 -> g_yh ----
    float inv0 = 1.f / l0, inv1 = 1.f / l1;
    const int t0 = qi * 128 + wbase + g;
    const int t1 = t0 + 8;
    uint32_t* y0 = g_yh + ((size_t)b * TT + t0) * (CC/2) + h * (DD/2);
    uint32_t* y1 = g_yh + ((size_t)b * TT + t1) * (CC/2) + h * (DD/2);
    #pragma unroll
    for (int nf = 0; nf < 8; nf++) {
        int d2 = nf * 4 + t;
        y0[d2] = pack_half2(of[nf][0] * inv0, of[nf][1] * inv0);
        y1[d2] = pack_half2(of[nf][2] * inv1, of[nf][3] * inv1);
    }
}

// ---------------------------------------------------------------------------
extern "C" void kernel_launch(void* const* d_in, const int* in_sizes, int n_in,
                              void* d_out, int out_size)
{
    const float* x      = (const float*)d_in[0];
    const float* w_qkv  = (const float*)d_in[1];
    const float* w_proj = (const float*)d_in[2];
    const float* b_proj = (const float*)d_in[3];
    float* out = (float*)d_out;

    static bool attr_set = false;
    if (!attr_set) {
        cudaFuncSetAttribute(flash_attn_f16_kernel,
                             cudaFuncAttributeMaxDynamicSharedMemorySize,
                             FA_SMEM_BYTES);
        cudaFuncSetAttribute(qkv_mma_kernel,
                             cudaFuncAttributeMaxDynamicSharedMemorySize,
                             GEMM_SMEM_BYTES);
        cudaFuncSetAttribute(proj_mma_kernel,
                             cudaFuncAttributeMaxDynamicSharedMemorySize,
                             GEMM_SMEM_BYTES);
        attr_set = true;
    }

    uint32_t* xh;  cudaGetSymbolAddress((void**)&xh,  g_xh);
    uint32_t* wqh; cudaGetSymbolAddress((void**)&wqh, g_wqh);
    uint32_t* wph; cudaGetSymbolAddress((void**)&wph, g_wph);

    // 0) input conversion
    conv_f16_kernel<<<1184, 256>>>((const float4*)x, (uint2*)xh, MROWS * CC / 4);
    {
        dim3 grid(3 * CC / 32, CC / 32);
        trans_f16_kernel<<<grid, 256>>>(w_qkv, wqh, 3 * CC, CC);
    }
    {
        dim3 grid(CC / 32, CC / 32);
        trans_f16_kernel<<<grid, 256>>>(w_proj, wph, CC, CC);
    }

    // 1) QKV projection + scatter
    {
        dim3 grid(3 * CC / 128, MROWS / 128);
        qkv_mma_kernel<<<grid, 256, GEMM_SMEM_BYTES>>>();
    }
    // 2) flash attention
    {
        dim3 grid(TT / 128, BB * HH);
        flash_attn_f16_kernel<<<grid, 256, FA_SMEM_BYTES>>>();
    }
    // 3) output projection + bias
    {
        dim3 grid(CC / 128, MROWS / 128);
        proj_mma_kernel<<<grid, 256, GEMM_SMEM_BYTES>>>(b_proj, out);
    }
}

// round 15
// speedup vs baseline: 1.5127x; 1.5127x over previous
#include <cuda_runtime.h>
#include <cuda_fp16.h>
#include <cstdint>

// Problem constants
#define BB   2
#define TT   2048
#define CC   1024
#define HH   16
#define DD   64
#define MROWS (BB*TT)          // 4096
#define SCALE 0.125f           // 1/sqrt(64)

// Scratch (device globals). fp16 data stored as packed u32 (half2 pairs).
__device__ uint32_t g_xh [MROWS*CC/2];     // x fp16 [M][C]
__device__ uint32_t g_wqh[3*CC*CC/2];      // w_qkv^T fp16 [3C][C]  ([n][k])
__device__ uint32_t g_wph[CC*CC/2];        // w_proj^T fp16 [C][C]
__device__ uint32_t g_q  [BB*HH*TT*DD/2];  // [bh][t][d] fp16
__device__ uint32_t g_k  [BB*HH*TT*DD/2];  // [bh][t][d] fp16
__device__ uint32_t g_vt [BB*HH*DD*TT/2];  // V^T: [bh][d][t] fp16
__device__ uint32_t g_yh [MROWS*CC/2];     // attention out fp16 [M][C]

// ===========================================================================
// helpers
// ===========================================================================
__device__ __forceinline__ uint32_t pack_half2(float lo, float hi) {
    uint32_t u;
    asm("cvt.rn.f16x2.f32 %0, %1, %2;" : "=r"(u) : "f"(hi), "f"(lo));
    return u;
}

__device__ __forceinline__ void mma_f16_16x8x16(float* c, const uint32_t* a,
                                                const uint32_t* b) {
    asm volatile(
        "mma.sync.aligned.m16n8k16.row.col.f32.f16.f16.f32 "
        "{%0,%1,%2,%3}, {%4,%5,%6,%7}, {%8,%9}, {%0,%1,%2,%3};\n"
        : "+f"(c[0]), "+f"(c[1]), "+f"(c[2]), "+f"(c[3])
        : "r"(a[0]), "r"(a[1]), "r"(a[2]), "r"(a[3]),
          "r"(b[0]), "r"(b[1]));
}

__device__ __forceinline__ void ldsm_x4(uint32_t* r, uint32_t saddr) {
    asm volatile("ldmatrix.sync.aligned.m8n8.x4.shared.b16 {%0,%1,%2,%3}, [%4];"
        : "=r"(r[0]), "=r"(r[1]), "=r"(r[2]), "=r"(r[3]) : "r"(saddr));
}

__device__ __forceinline__ void cp_async16(uint32_t dst, const void* src) {
    asm volatile("cp.async.cg.shared.global [%0], [%1], 16;"
                 :: "r"(dst), "l"(src));
}
__device__ __forceinline__ void cp_commit() {
    asm volatile("cp.async.commit_group;" ::: "memory");
}
__device__ __forceinline__ void cp_wait2() {
    asm volatile("cp.async.wait_group 2;" ::: "memory");
}

// ---------------------------------------------------------------------------
// Kernel 0a: fp32 -> fp16 bulk convert
// ---------------------------------------------------------------------------
__global__ __launch_bounds__(256) void conv_f16_kernel(
    const float4* __restrict__ in, uint2* __restrict__ out, int n4)
{
    int i = blockIdx.x * blockDim.x + threadIdx.x;
    int stride = gridDim.x * blockDim.x;
    for (; i < n4; i += stride) {
        float4 v = in[i];
        uint2 o;
        o.x = pack_half2(v.x, v.y);
        o.y = pack_half2(v.z, v.w);
        out[i] = o;
    }
}

// ---------------------------------------------------------------------------
// Kernel 0b: fp32 [K][N] -> fp16 [N][K] transpose (weights)
// ---------------------------------------------------------------------------
__global__ __launch_bounds__(256) void trans_f16_kernel(
    const float* __restrict__ in, uint32_t* __restrict__ out, int N, int K)
{
    __shared__ float ts[32][33];
    const int k0 = blockIdx.y * 32, n0 = blockIdx.x * 32;
    const int tx = threadIdx.x & 31, ty = threadIdx.x >> 5;
    #pragma unroll
    for (int j = 0; j < 4; j++)
        ts[ty + 8*j][tx] = in[(size_t)(k0 + ty + 8*j) * N + n0 + tx];
    __syncthreads();
    const int n = threadIdx.x >> 3, c = threadIdx.x & 7;
    out[(size_t)(n0 + n) * (K >> 1) + (k0 >> 1) + c] =
        pack_half2(ts[2*c][n], ts[2*c + 1][n]);
    out[(size_t)(n0 + n) * (K >> 1) + (k0 >> 1) + c + 8] =
        pack_half2(ts[2*c + 16][n], ts[2*c + 17][n]);
}

// ===========================================================================
// fp16 GEMM mainloop, cp.async 4-stage + ldmatrix (unchanged from R13).
// ===========================================================================
#define GP 20
#define GSTA (128*GP)
#define GST (2*GSTA)
#define NSTAGE 4
#define GEMM_SMEM_BYTES (NSTAGE * GST * 4)   // 81920 B

__device__ __forceinline__ void gemm_f16_mainloop(
    uint32_t* sm, const uint32_t* __restrict__ A,
    const uint32_t* __restrict__ B, float acc[2][8][4])
{
    const int tid = threadIdx.x;
    const int wid = tid >> 5, lane = tid & 31;
    const int warp_m = wid & 3;
    const int warp_n = wid >> 2;

    #pragma unroll
    for (int mi = 0; mi < 2; mi++)
        #pragma unroll
        for (int ni = 0; ni < 8; ni++)
            #pragma unroll
            for (int r = 0; r < 4; r++) acc[mi][ni][r] = 0.f;

    const int r0 = tid >> 2, s0 = tid & 3;
    const int r1 = (256 + tid) >> 2, s1 = tid & 3;
    const uint32_t smaddr = (uint32_t)__cvta_generic_to_shared(sm);

    #pragma unroll
    for (int s = 0; s < NSTAGE - 1; s++) {
        const uint32_t so = (uint32_t)(s * GST * 4);
        cp_async16(smaddr + so + (uint32_t)(r0 * GP + s0 * 4) * 4,
                   A + (size_t)r0 * (CC/2) + s * 16 + s0 * 4);
        cp_async16(smaddr + so + (uint32_t)(r1 * GP + s1 * 4) * 4,
                   A + (size_t)r1 * (CC/2) + s * 16 + s1 * 4);
        cp_async16(smaddr + so + (uint32_t)(GSTA + r0 * GP + s0 * 4) * 4,
                   B + (size_t)r0 * (CC/2) + s * 16 + s0 * 4);
        cp_async16(smaddr + so + (uint32_t)(GSTA + r1 * GP + s1 * 4) * 4,
                   B + (size_t)r1 * (CC/2) + s * 16 + s1 * 4);
        cp_commit();
    }

    const int lq = lane >> 3, lr = lane & 7;
    const int a_row  = warp_m * 32 + lr + 8 * (lq & 1);
    const int a_col  = 4 * (lq >> 1);
    const int b_row  = warp_n * 64 + lr + 8 * (lq >> 1);
    const int b_col  = 4 * (lq & 1);

    for (int c = 0; c < CC / 32; c++) {
        cp_wait2();
        __syncthreads();

        const uint32_t sa = smaddr + (uint32_t)((c & 3) * GST) * 4;
        const uint32_t sb = sa + (uint32_t)GSTA * 4;

        uint32_t af[2][2][4];
        #pragma unroll
        for (int mi = 0; mi < 2; mi++)
            #pragma unroll
            for (int ks = 0; ks < 2; ks++)
                ldsm_x4(af[mi][ks],
                        sa + (uint32_t)((a_row + mi * 16) * GP + ks * 8 + a_col) * 4);

        uint32_t bf[4][2][4];
        #pragma unroll
        for (int nfp = 0; nfp < 4; nfp++)
            #pragma unroll
            for (int ks = 0; ks < 2; ks++)
                ldsm_x4(bf[nfp][ks],
                        sb + (uint32_t)((b_row + nfp * 16) * GP + ks * 8 + b_col) * 4);

        #pragma unroll
        for (int mi = 0; mi < 2; mi++)
            #pragma unroll
            for (int nfp = 0; nfp < 4; nfp++)
                #pragma unroll
                for (int ks = 0; ks < 2; ks++) {
                    mma_f16_16x8x16(acc[mi][2 * nfp],     af[mi][ks], &bf[nfp][ks][0]);
                    mma_f16_16x8x16(acc[mi][2 * nfp + 1], af[mi][ks], &bf[nfp][ks][2]);
                }

        if (c + NSTAGE - 1 < CC / 32) {
            const int cn = c + NSTAGE - 1;
            const uint32_t so = (uint32_t)((cn & 3) * GST * 4);
            cp_async16(smaddr + so + (uint32_t)(r0 * GP + s0 * 4) * 4,
                       A + (size_t)r0 * (CC/2) + cn * 16 + s0 * 4);
            cp_async16(smaddr + so + (uint32_t)(r1 * GP + s1 * 4) * 4,
                       A + (size_t)r1 * (CC/2) + cn * 16 + s1 * 4);
            cp_async16(smaddr + so + (uint32_t)(GSTA + r0 * GP + s0 * 4) * 4,
                       B + (size_t)r0 * (CC/2) + cn * 16 + s0 * 4);
            cp_async16(smaddr + so + (uint32_t)(GSTA + r1 * GP + s1 * 4) * 4,
                       B + (size_t)r1 * (CC/2) + cn * 16 + s1 * 4);
        }
        cp_commit();
    }
}

// ---------------------------------------------------------------------------
// Kernel 1: QKV projection (unchanged from R13)
// ---------------------------------------------------------------------------
__global__ __launch_bounds__(256, 2) void qkv_mma_kernel()
{
    extern __shared__ uint32_t smu[];
    const int bx = blockIdx.x;
    const int by = blockIdx.y;
    const int tid = threadIdx.x;
    const int wid = tid >> 5, lane = tid & 31;
    const int warp_m = wid & 3, warp_n = wid >> 2;
    const int g = lane >> 2, t = lane & 3;

    float acc[2][8][4];
    gemm_f16_mainloop(smu, g_xh + (size_t)(by * 128) * (CC/2),
                      g_wqh + (size_t)(bx * 128) * (CC/2), acc);

    const int g3 = bx >> 3;
    if (g3 < 2) {
        uint32_t* dstbase = (g3 == 0) ? g_q : g_k;
        #pragma unroll
        for (int mi = 0; mi < 2; mi++) {
            #pragma unroll
            for (int rr = 0; rr < 2; rr++) {
                int m = by * 128 + warp_m * 32 + mi * 16 + g + rr * 8;
                int b = m >> 11, tloc = m & (TT - 1);
                #pragma unroll
                for (int ni = 0; ni < 8; ni++) {
                    int n = bx * 128 + warp_n * 64 + ni * 8 + 2 * t;
                    int rem = n & 1023;
                    int h = rem >> 6, d = rem & 63;
                    dstbase[(((size_t)(b * HH + h)) * TT + tloc) * (DD/2) + (d >> 1)] =
                        pack_half2(acc[mi][ni][rr * 2], acc[mi][ni][rr * 2 + 1]);
                }
            }
        }
    } else {
        unsigned short* vt = (unsigned short*)g_vt;
        #pragma unroll
        for (int mi = 0; mi < 2; mi++) {
            #pragma unroll
            for (int rr = 0; rr < 2; rr++) {
                int m = by * 128 + warp_m * 32 + mi * 16 + g + rr * 8;
                int b = m >> 11, tloc = m & (TT - 1);
                #pragma unroll
                for (int ni = 0; ni < 8; ni++) {
                    int n = bx * 128 + warp_n * 64 + ni * 8 + 2 * t;
                    int rem = n & 1023;
                    int h = rem >> 6, d = rem & 63;
                    size_t base = ((size_t)(b * HH + h) * DD + d) * TT + tloc;
                    vt[base]      = __half_as_ushort(__float2half_rn(acc[mi][ni][rr * 2]));
                    vt[base + TT] = __half_as_ushort(__float2half_rn(acc[mi][ni][rr * 2 + 1]));
                }
            }
        }
    }
}

// ---------------------------------------------------------------------------
// Kernel 3: out = y @ w_proj + b_proj (unchanged from R13)
// ---------------------------------------------------------------------------
__global__ __launch_bounds__(256, 2) void proj_mma_kernel(
    const float* __restrict__ bias, float* __restrict__ out)
{
    extern __shared__ uint32_t smu[];
    const int bx = blockIdx.x;
    const int by = blockIdx.y;
    const int tid = threadIdx.x;
    const int wid = tid >> 5, lane = tid & 31;
    const int warp_m = wid & 3, warp_n = wid >> 2;
    const int g = lane >> 2, t = lane & 3;

    float acc[2][8][4];
    gemm_f16_mainloop(smu, g_yh + (size_t)(by * 128) * (CC/2),
                      g_wph + (size_t)(bx * 128) * (CC/2), acc);

    #pragma unroll
    for (int mi = 0; mi < 2; mi++) {
        #pragma unroll
        for (int rr = 0; rr < 2; rr++) {
            int m = by * 128 + warp_m * 32 + mi * 16 + g + rr * 8;
            #pragma unroll
            for (int ni = 0; ni < 8; ni++) {
                int n = bx * 128 + warp_n * 64 + ni * 8 + 2 * t;
                float2 v2;
                v2.x = acc[mi][ni][rr * 2]     + bias[n];
                v2.y = acc[mi][ni][rr * 2 + 1] + bias[n + 1];
                *(float2*)&out[(size_t)m * CC + n] = v2;
            }
        }
    }
}

// ===========================================================================
// Flash attention, fp16 mma. R13 pipeline (LDG register-staged double buffer,
// one __syncthreads per tile) + ldmatrix b-frag loads (validated in R14).
// ===========================================================================
#define ATP 36
#define AST (64*ATP*2)                    // stage u32 = 4608
#define FA_SMEM_BYTES (2 * AST * 4)       // 36864

__global__ __launch_bounds__(256, 2) void flash_attn_f16_kernel()
{
    extern __shared__ uint32_t smu[];
    const uint32_t smaddr = (uint32_t)__cvta_generic_to_shared(smu);

    const int qi = (int)gridDim.x - 1 - (int)blockIdx.x;   // heavy CTAs first
    const int bh = blockIdx.y;
    const int b = bh >> 4, h = bh & 15;
    const int tid = threadIdx.x;
    const int wid = tid >> 5, lane = tid & 31;
    const int g = lane >> 2, t = lane & 3;
    const int wbase = wid * 16;

    // ---- Q fragments straight from gmem ----
    const uint32_t* q0 = g_q + ((size_t)bh * TT + qi * 128 + wbase + g) * (DD/2);
    const uint32_t* q1 = q0 + 8 * (DD/2);
    uint32_t qf[4][4];
    #pragma unroll
    for (int ks = 0; ks < 4; ks++) {
        qf[ks][0] = q0[ks * 8 + t];
        qf[ks][1] = q1[ks * 8 + t];
        qf[ks][2] = q0[ks * 8 + t + 4];
        qf[ks][3] = q1[ks * 8 + t + 4];
    }

    const int nkt = 2 * qi + 2;
    const int krow = tid >> 2, u = tid & 3;     // K: key row / V: d row

    // ---- prologue: FULL tile 0 -> stage 0 (two uint4 per thread) ----
    uint4 rk[2], rv[2];
    {
        const uint32_t* kp = g_k + ((size_t)bh * TT + krow) * (DD/2);
        const uint32_t* vp = g_vt + ((size_t)bh * DD + krow) * (TT/2);
        rk[0] = *(const uint4*)(kp + u * 4);
        rk[1] = *(const uint4*)(kp + u * 4 + 16);
        rv[0] = *(const uint4*)(vp + u * 4);
        rv[1] = *(const uint4*)(vp + u * 4 + 16);
        uint32_t* Kh = smu;
        uint32_t* Vh = smu + 64 * ATP;
        *(uint4*)&Kh[krow * ATP + u * 4]      = rk[0];
        *(uint4*)&Kh[krow * ATP + u * 4 + 16] = rk[1];
        *(uint4*)&Vh[krow * ATP + u * 4]      = rv[0];
        *(uint4*)&Vh[krow * ATP + u * 4 + 16] = rv[1];
    }
    __syncthreads();

    // ldmatrix lane addressing (validated mapping from R14)
    const int lq = lane >> 3, lr = lane & 7;
    const int f_row  = lr + 8 * (lq >> 1);   // + nfp*16
    const int f_col4 = 4 * (lq & 1);          // + ks*8

    float of[8][4];
    #pragma unroll
    for (int nf = 0; nf < 8; nf++)
        #pragma unroll
        for (int r = 0; r < 4; r++) of[nf][r] = 0.f;
    float m0 = -1e30f, m1 = -1e30f, l0 = 0.f, l1 = 0.f;

    const int qrow0 = qi * 128 + wbase + g;
    const int qrow1 = qrow0 + 8;

    for (int kt = 0; kt < nkt; kt++) {
        const uint32_t sk = smaddr + (uint32_t)((kt & 1) * AST) * 4;
        const uint32_t sv = sk + (uint32_t)(64 * ATP) * 4;
        const bool more = (kt + 1 < nkt);

        if (more) {
            const uint32_t* kp = g_k + ((size_t)bh * TT + (kt + 1) * 64 + krow) * (DD/2);
            const uint32_t* vp = g_vt + ((size_t)bh * DD + krow) * (TT/2) + (kt + 1) * 32;
            rk[0] = *(const uint4*)(kp + u * 4);
            rk[1] = *(const uint4*)(kp + u * 4 + 16);
            rv[0] = *(const uint4*)(vp + u * 4);
            rv[1] = *(const uint4*)(vp + u * 4 + 16);
        }

        // ---- S = Q @ K^T (ldmatrix b-frags) ----
        float sf[8][4];
        #pragma unroll
        for (int nf = 0; nf < 8; nf++)
            #pragma unroll
            for (int r = 0; r < 4; r++) sf[nf][r] = 0.f;

        #pragma unroll
        for (int ks = 0; ks < 4; ks++) {
            #pragma unroll
            for (int nfp = 0; nfp < 4; nfp++) {
                uint32_t bfr[4];
                ldsm_x4(bfr, sk + (uint32_t)((nfp * 16 + f_row) * ATP + ks * 8 + f_col4) * 4);
                mma_f16_16x8x16(sf[2 * nfp],     qf[ks], &bfr[0]);
                mma_f16_16x8x16(sf[2 * nfp + 1], qf[ks], &bfr[2]);
            }
        }

        // ---- scale + causal mask ----
        const bool need_mask = (kt >= 2 * qi);
        #pragma unroll
        for (int nf = 0; nf < 8; nf++) {
            int kc0 = kt * 64 + nf * 8 + 2 * t;
            int kc1 = kc0 + 1;
            if (need_mask) {
                sf[nf][0] = (kc0 <= qrow0) ? sf[nf][0] * SCALE : -1e30f;
                sf[nf][1] = (kc1 <= qrow0) ? sf[nf][1] * SCALE : -1e30f;
                sf[nf][2] = (kc0 <= qrow1) ? sf[nf][2] * SCALE : -1e30f;
                sf[nf][3] = (kc1 <= qrow1) ? sf[nf][3] * SCALE : -1e30f;
            } else {
                sf[nf][0] *= SCALE; sf[nf][1] *= SCALE;
                sf[nf][2] *= SCALE; sf[nf][3] *= SCALE;
            }
        }

        // ---- online softmax ----
        float mx0 = -1e30f, mx1 = -1e30f;
        #pragma unroll
        for (int nf = 0; nf < 8; nf++) {
            mx0 = fmaxf(mx0, fmaxf(sf[nf][0], sf[nf][1]));
            mx1 = fmaxf(mx1, fmaxf(sf[nf][2], sf[nf][3]));
        }
        #pragma unroll
        for (int off = 1; off < 4; off <<= 1) {
            mx0 = fmaxf(mx0, __shfl_xor_sync(0xffffffffu, mx0, off));
            mx1 = fmaxf(mx1, __shfl_xor_sync(0xffffffffu, mx1, off));
        }
        float mn0 = fmaxf(m0, mx0), mn1 = fmaxf(m1, mx1);
        float a0 = __expf(m0 - mn0), a1 = __expf(m1 - mn1);
        m0 = mn0; m1 = mn1;

        float s0 = 0.f, s1 = 0.f;
        #pragma unroll
        for (int nf = 0; nf < 8; nf++) {
            sf[nf][0] = __expf(sf[nf][0] - mn0);
            sf[nf][1] = __expf(sf[nf][1] - mn0);
            sf[nf][2] = __expf(sf[nf][2] - mn1);
            sf[nf][3] = __expf(sf[nf][3] - mn1);
            s0 += sf[nf][0] + sf[nf][1];
            s1 += sf[nf][2] + sf[nf][3];
        }
        #pragma unroll
        for (int off = 1; off < 4; off <<= 1) {
            s0 += __shfl_xor_sync(0xffffffffu, s0, off);
            s1 += __shfl_xor_sync(0xffffffffu, s1, off);
        }
        l0 = l0 * a0 + s0;
        l1 = l1 * a1 + s1;

        // ---- P -> fp16 a-frags (registers only) ----
        uint32_t pf[4][4];
        #pragma unroll
        for (int ks = 0; ks < 4; ks++) {
            pf[ks][0] = pack_half2(sf[2*ks][0],     sf[2*ks][1]);
            pf[ks][1] = pack_half2(sf[2*ks][2],     sf[2*ks][3]);
            pf[ks][2] = pack_half2(sf[2*ks + 1][0], sf[2*ks + 1][1]);
            pf[ks][3] = pack_half2(sf[2*ks + 1][2], sf[2*ks + 1][3]);
        }

        // ---- store next K/V into the other stage ----
        if (more) {
            uint32_t* Ksn = smu + ((kt + 1) & 1) * AST;
            uint32_t* Vsn = Ksn + 64 * ATP;
            *(uint4*)&Ksn[krow * ATP + u * 4]      = rk[0];
            *(uint4*)&Ksn[krow * ATP + u * 4 + 16] = rk[1];
            *(uint4*)&Vsn[krow * ATP + u * 4]      = rv[0];
            *(uint4*)&Vsn[krow * ATP + u * 4 + 16] = rv[1];
        }

        // ---- rescale O, then O += P @ V (ldmatrix b-frags) ----
        #pragma unroll
        for (int nf = 0; nf < 8; nf++) {
            of[nf][0] *= a0; of[nf][1] *= a0;
            of[nf][2] *= a1; of[nf][3] *= a1;
        }
        #pragma unroll
        for (int ks = 0; ks < 4; ks++) {
            #pragma unroll
            for (int nfp = 0; nfp < 4; nfp++) {
                uint32_t bfr[4];
                ldsm_x4(bfr, sv + (uint32_t)((nfp * 16 + f_row) * ATP + ks * 8 + f_col4) * 4);
                mma_f16_16x8x16(of[2 * nfp],     pf[ks], &bfr[0]);
                mma_f16_16x8x16(of[2 * nfp + 1], pf[ks], &bfr[2]);
            }
        }
        __syncthreads();
    }

    // ---- epilogue: normalize -> fp16 -> g_yh ----
    float inv0 = 1.f / l0, inv1 = 1.f / l1;
    const int t0 = qi * 128 + wbase + g;
    const int t1 = t0 + 8;
    uint32_t* y0 = g_yh + ((size_t)b * TT + t0) * (CC/2) + h * (DD/2);
    uint32_t* y1 = g_yh + ((size_t)b * TT + t1) * (CC/2) + h * (DD/2);
    #pragma unroll
    for (int nf = 0; nf < 8; nf++) {
        int d2 = nf * 4 + t;
        y0[d2] = pack_half2(of[nf][0] * inv0, of[nf][1] * inv0);
        y1[d2] = pack_half2(of[nf][2] * inv1, of[nf][3] * inv1);
    }
}

// ---------------------------------------------------------------------------
extern "C" void kernel_launch(void* const* d_in, const int* in_sizes, int n_in,
                              void* d_out, int out_size)
{
    const float* x      = (const float*)d_in[0];
    const float* w_qkv  = (const float*)d_in[1];
    const float* w_proj = (const float*)d_in[2];
    const float* b_proj = (const float*)d_in[3];
    float* out = (float*)d_out;

    static bool attr_set = false;
    if (!attr_set) {
        cudaFuncSetAttribute(flash_attn_f16_kernel,
                             cudaFuncAttributeMaxDynamicSharedMemorySize,
                             FA_SMEM_BYTES);
        cudaFuncSetAttribute(qkv_mma_kernel,
                             cudaFuncAttributeMaxDynamicSharedMemorySize,
                             GEMM_SMEM_BYTES);
        cudaFuncSetAttribute(proj_mma_kernel,
                             cudaFuncAttributeMaxDynamicSharedMemorySize,
                             GEMM_SMEM_BYTES);
        attr_set = true;
    }

    uint32_t* xh;  cudaGetSymbolAddress((void**)&xh,  g_xh);
    uint32_t* wqh; cudaGetSymbolAddress((void**)&wqh, g_wqh);
    uint32_t* wph; cudaGetSymbolAddress((void**)&wph, g_wph);

    // 0) input conversion
    conv_f16_kernel<<<1184, 256>>>((const float4*)x, (uint2*)xh, MROWS * CC / 4);
    {
        dim3 grid(3 * CC / 32, CC / 32);
        trans_f16_kernel<<<grid, 256>>>(w_qkv, wqh, 3 * CC, CC);
    }
    {
        dim3 grid(CC / 32, CC / 32);
        trans_f16_kernel<<<grid, 256>>>(w_proj, wph, CC, CC);
    }

    // 1) QKV projection + scatter
    {
        dim3 grid(3 * CC / 128, MROWS / 128);
        qkv_mma_kernel<<<grid, 256, GEMM_SMEM_BYTES>>>();
    }
    // 2) flash attention
    {
        dim3 grid(TT / 128, BB * HH);
        flash_attn_f16_kernel<<<grid, 256, FA_SMEM_BYTES>>>();
    }
    // 3) output projection + bias
    {
        dim3 grid(CC / 128, MROWS / 128);
        proj_mma_kernel<<<grid, 256, GEMM_SMEM_BYTES>>>(b_proj, out);
    }
}